// round 15
// baseline (speedup 1.0000x reference)
#include <cuda_runtime.h>
#include <math.h>

#define B 16
#define CIN 3
#define DIM 128
#define KCODES 512
#define H0 256
#define H1 128
#define H2 64
#define OFF_ZE  (B*CIN*H0*H0)
#define OFF_ZQ  (OFF_ZE + B*DIM*H2*H2)

__device__ float g_h[B*DIM*H1*H1];
__device__ float g_g[B*DIM*H1*H1];
__device__ float g_cnorm[KCODES];
__device__ int   g_idx[B*H2*H2];
__device__ float g_T[513*16*128];
__device__ unsigned long long g_W2[CIN*2048];   // deconv2 weights, permuted+duplicated

typedef unsigned long long u64;
typedef unsigned int u32;
__device__ __forceinline__ void fma2(u64& d, u64 a, u64 b) {
    asm("fma.rn.f32x2 %0, %1, %2, %0;" : "+l"(d) : "l"(a), "l"(b));
}
__device__ __forceinline__ u64 pack2(float lo, float hi) {
    u64 r; asm("mov.b64 %0, {%1, %2};" : "=l"(r) : "f"(lo), "f"(hi)); return r;
}
__device__ __forceinline__ float2 unpack2(u64 v) {
    float2 r; asm("mov.b64 {%0, %1}, %2;" : "=f"(r.x), "=f"(r.y) : "l"(v)); return r;
}
__device__ __forceinline__ u64 lds2(const float* p) { return *(const u64*)p; }
__device__ __forceinline__ u32 cvta_s(const void* p) {
    u32 a; asm("{.reg .u64 t; cvta.to.shared.u64 t, %1; cvt.u32.u64 %0, t;}" : "=r"(a) : "l"(p));
    return a;
}
__device__ __forceinline__ void cp16(u32 d, const void* s) {
    asm volatile("cp.async.ca.shared.global [%0], [%1], 16;" :: "r"(d), "l"(s));
}
__device__ __forceinline__ void cp4z(u32 d, const void* s, int sz) {
    asm volatile("cp.async.ca.shared.global [%0], [%1], 4, %2;" :: "r"(d), "l"(s), "r"(sz));
}
#define CP_COMMIT() asm volatile("cp.async.commit_group;" ::: "memory")
#define CP_WAIT0()  asm volatile("cp.async.wait_group 0;" ::: "memory")

__global__ void knorm_kernel(const float* __restrict__ emb) {
    int k = blockIdx.x * blockDim.x + threadIdx.x;
    if (k < KCODES) {
        const float* e = emb + k * DIM;
        float s = 0.f;
#pragma unroll 8
        for (int d = 0; d < DIM; d++) s += e[d] * e[d];
        g_cnorm[k] = s;
    }
}

// one-time: permute + duplicate deconv2 weights
__global__ void wd2dup_kernel(const float* __restrict__ w) {
    int i = blockIdx.x * blockDim.x + threadIdx.x;
    if (i < CIN * DIM * 16) {
        int oc = i >> 11, rem = i & 2047;
        int ic = rem >> 4, k = rem & 15, kh = k >> 2, kw = k & 3;
        int slot = ic * 16 + ((kh & 1) * 2 + (kw & 1)) * 4 + ((kh >> 1) << 1) + (kw >> 1);
        float v = w[i];
        g_W2[oc * 2048 + slot] = pack2(v, v);
    }
}

__global__ __launch_bounds__(256) void tmat_kernel(
    const float* __restrict__ emb, const float* __restrict__ wd1) {
    __shared__ float ws[2048];
    int oc = blockIdx.x, tid = threadIdx.x;
    for (int i = tid; i < 2048; i += 256) ws[i] = wd1[oc * 2048 + i];
    __syncthreads();
    for (int k = tid; k < 513; k += 256) {
        float acc[16];
#pragma unroll
        for (int t = 0; t < 16; t++) acc[t] = 0.f;
        if (k < 512) {
            const float* e = emb + k * DIM;
            for (int ic = 0; ic < 128; ic++) {
                float ev = __ldg(e + ic);
                const float* wp = &ws[ic * 16];
#pragma unroll
                for (int t = 0; t < 16; t++) acc[t] += ev * wp[t];
            }
        }
#pragma unroll
        for (int t = 0; t < 16; t++) g_T[(k * 16 + t) * 128 + oc] = acc[t];
    }
}

// conv1 (unchanged from R14)
__global__ __launch_bounds__(256) void conv1_kernel(
    const float* __restrict__ x, const float* __restrict__ w) {
    __shared__ float ws[DIM * 48];
    __shared__ float ins[CIN][6][260];
    int n = blockIdx.y, oy0 = blockIdx.x * 2, tid = threadIdx.x;
    for (int i = tid; i < DIM * 48; i += 256) ws[i] = w[i];
    int iyb = oy0 * 2 - 1;
    for (int i = tid; i < CIN * 6 * 258; i += 256) {
        int ic = i / 1548, rem = i - ic * 1548, r = rem / 258, c = rem - r * 258;
        int iy = iyb + r, ix = c - 1;
        float v = 0.f;
        if ((unsigned)iy < H0 && (unsigned)ix < H0) v = x[((n * CIN + ic) * H0 + iy) * H0 + ix];
        ins[ic][r][c] = v;
    }
    __syncthreads();
    int oc = tid >> 1, half = tid & 1;
    u64 wp[24];
#pragma unroll
    for (int ic = 0; ic < 3; ic++)
#pragma unroll
        for (int kh = 0; kh < 4; kh++) {
            const float* wk = &ws[oc * 48 + ic * 16 + kh * 4];
            wp[(ic * 4 + kh) * 2] = pack2(wk[0], wk[1]);
            wp[(ic * 4 + kh) * 2 + 1] = pack2(wk[2], wk[3]);
        }
#pragma unroll
    for (int ry = 0; ry < 2; ry++) {
        float* outp = g_h + ((n * DIM + oc) * H1 + oy0 + ry) * H1;
        for (int k = 0; k < 64; k += 4) {
            int oxa = half + 2 * k;
            u64 a0 = 0, a1 = 0, a2 = 0, a3 = 0;
#pragma unroll
            for (int ic = 0; ic < 3; ic++)
#pragma unroll
                for (int kh = 0; kh < 4; kh++) {
                    const float* rp = &ins[ic][2 * ry + kh][2 * oxa];
                    u64 w01 = wp[(ic * 4 + kh) * 2], w23 = wp[(ic * 4 + kh) * 2 + 1];
                    fma2(a0, lds2(rp),      w01); fma2(a0, lds2(rp + 2),  w23);
                    fma2(a1, lds2(rp + 4),  w01); fma2(a1, lds2(rp + 6),  w23);
                    fma2(a2, lds2(rp + 8),  w01); fma2(a2, lds2(rp + 10), w23);
                    fma2(a3, lds2(rp + 12), w01); fma2(a3, lds2(rp + 14), w23);
                }
            float2 v0 = unpack2(a0), v1 = unpack2(a1), v2 = unpack2(a2), v3 = unpack2(a3);
            outp[oxa]     = fmaxf(v0.x + v0.y, 0.f);
            outp[oxa + 2] = fmaxf(v1.x + v1.y, 0.f);
            outp[oxa + 4] = fmaxf(v2.x + v2.y, 0.f);
            outp[oxa + 6] = fmaxf(v3.x + v3.y, 0.f);
        }
    }
}

// conv2 (unchanged — at FFMA2 floor)
#define C2_TBL_F 3072
#define C2_WS_F  8704
#define C2_BUF_F (C2_WS_F + 1584)
#define C2_SMEM  ((C2_TBL_F + 2 * C2_BUF_F) * 4)

__global__ __launch_bounds__(256, 2) void conv2_kernel(
    const float* __restrict__ w, float* __restrict__ ze) {
    extern __shared__ float s2[];
    uint2* tbl = (uint2*)s2;
    float* bufs = s2 + C2_TBL_F;
    int tid = threadIdx.x;
    int n = blockIdx.z, oy0 = blockIdx.y * 8, ox0 = blockIdx.x * 8;
    int ocg = tid >> 3, oyl = tid & 7;
    int iyb = oy0 * 2 - 1, ixb = ox0 * 2 - 1;
    u32 sbase = cvta_s(bufs);

    uint2* myt = tbl + tid * 6;
#pragma unroll
    for (int j = 0; j < 6; j++) {
        int i = tid + j * 256;
        u32 gof = 0, sof = (u32)((C2_WS_F + 19) * 4);
        if (i < 1296) {
            int ic = i / 324, rem = i - ic * 324, r = rem / 18, c = rem - r * 18;
            int iy = iyb + r, ix = ixb + c;
            bool ok = ((unsigned)iy < H1) && ((unsigned)ix < H1);
            sof = (u32)((C2_WS_F + ic * 396 + r * 22 + c) * 4) | (ok ? 1u : 0u);
            if (ok) gof = (u32)(((n * DIM + ic) * H1 + iy) * H1 + ix);
        }
        myt[j] = make_uint2(gof, sof);
    }
    int woc0 = tid >> 4;
    u32 wdofs = (u32)(woc0 * 68 * 4 + (tid & 15) * 16);
    const float* wsrc = w + woc0 * 2048 + (tid & 15) * 4;

    u64 acc[4][8];
#pragma unroll
    for (int o = 0; o < 4; o++)
#pragma unroll
        for (int j = 0; j < 8; j++) acc[o][j] = 0;

    {
        u32 bb = sbase;
#pragma unroll
        for (int jj = 0; jj < 8; jj++)
            cp16(bb + wdofs + jj * (16 * 68 * 4), wsrc + jj * (16 * 2048));
#pragma unroll
        for (int jj = 0; jj < 5; jj++) {
            uint2 e = myt[jj];
            cp4z(bb + (e.y & ~1u), g_h + e.x, (e.y & 1) * 4);
        }
        if (tid < 16) {
            uint2 e = myt[5];
            cp4z(bb + (e.y & ~1u), g_h + e.x, (e.y & 1) * 4);
        }
    }
    CP_COMMIT();

    for (int st = 0; st < 32; st++) {
        CP_WAIT0();
        __syncthreads();
        if (st < 31) {
            u32 bb = sbase + ((st + 1) & 1) * (C2_BUF_F * 4);
            const float* wsp = wsrc + (st + 1) * 64;
            const float* gbase = g_h + (st + 1) * 65536;
#pragma unroll
            for (int jj = 0; jj < 8; jj++)
                cp16(bb + wdofs + jj * (16 * 68 * 4), wsp + jj * (16 * 2048));
#pragma unroll
            for (int jj = 0; jj < 5; jj++) {
                uint2 e = myt[jj];
                cp4z(bb + (e.y & ~1u), gbase + e.x, (e.y & 1) * 4);
            }
            if (tid < 16) {
                uint2 e = myt[5];
                cp4z(bb + (e.y & ~1u), gbase + e.x, (e.y & 1) * 4);
            }
            CP_COMMIT();
        }
        float* wsb = bufs + (st & 1) * C2_BUF_F;
        float* insb = wsb + C2_WS_F;
#pragma unroll
        for (int icl = 0; icl < 4; icl++) {
#pragma unroll
            for (int kh = 0; kh < 4; kh++) {
                const float* rp = insb + icl * 396 + (oyl * 2 + kh) * 22;
                u64 ivp[9];
#pragma unroll
                for (int m = 0; m < 9; m++) ivp[m] = lds2(rp + 2 * m);
#pragma unroll
                for (int o = 0; o < 4; o++) {
                    const ulonglong2* wpt = (const ulonglong2*)
                        (wsb + (ocg * 4 + o) * 68 + icl * 16 + kh * 4);
                    ulonglong2 wv = *wpt;
#pragma unroll
                    for (int j = 0; j < 8; j++) {
                        fma2(acc[o][j], ivp[j], wv.x);
                        fma2(acc[o][j], ivp[j + 1], wv.y);
                    }
                }
            }
        }
    }
    int oy = oy0 + oyl;
#pragma unroll
    for (int o = 0; o < 4; o++) {
        float* op = ze + ((n * DIM + ocg * 4 + o) * H2 + oy) * H2 + ox0;
#pragma unroll
        for (int j = 0; j < 8; j++) {
            float2 v = unpack2(acc[o][j]);
            op[j] = v.x + v.y;
        }
    }
}

// VQ: code-pair packing (c pairs straight from LDS, z duplicated). Bitwise-same.
__global__ __launch_bounds__(256) void vq_kernel(
    const float* __restrict__ ze, const float* __restrict__ emb, float* __restrict__ zq) {
    extern __shared__ float sm[];
    float* z_s = sm;
    float* c_s = sm + 128 * 68;
    __shared__ int idx_s[64];
    int tid = threadIdx.x;
    int v0 = blockIdx.x * 64, b = v0 >> 12, s0 = v0 & 4095;
    for (int i = tid; i < 2048; i += 256) {
        int d = i >> 4, vl4 = (i & 15) * 4;
        *(float4*)&z_s[d * 68 + vl4] = *(const float4*)&ze[(b * DIM + d) * 4096 + s0 + vl4];
    }
    int vg = tid >> 4, cg = tid & 15;
    float minv[4]; int mini[4];
#pragma unroll
    for (int v = 0; v < 4; v++) { minv[v] = 3.0e38f; mini[v] = 0; }
    u64 dot[4][4];
#pragma unroll
    for (int v = 0; v < 4; v++)
#pragma unroll
        for (int p = 0; p < 4; p++) dot[v][p] = 0;
    for (int ch = 0; ch < 4; ch++) {
        __syncthreads();
        int cbase = ch * 128;
        for (int i = tid; i < 4096; i += 256) {
            int cl = i & 127, dq = (i >> 7) * 4;
            float4 t = *(const float4*)&emb[(cbase + cl) * DIM + dq];
            c_s[dq * 132 + cl] = t.x; c_s[(dq + 1) * 132 + cl] = t.y;
            c_s[(dq + 2) * 132 + cl] = t.z; c_s[(dq + 3) * 132 + cl] = t.w;
        }
        __syncthreads();
#pragma unroll 2
        for (int d = 0; d < 128; d++) {
            float4 z0 = *(const float4*)&z_s[d * 68 + vg * 4];
            u64 zd[4] = {pack2(z0.x, z0.x), pack2(z0.y, z0.y),
                         pack2(z0.z, z0.z), pack2(z0.w, z0.w)};
            const ulonglong2* cp2 = (const ulonglong2*)&c_s[d * 132 + cg * 8];
            ulonglong2 ca = cp2[0], cb2 = cp2[1];
            u64 cpair[4] = {ca.x, ca.y, cb2.x, cb2.y};
#pragma unroll
            for (int v = 0; v < 4; v++)
#pragma unroll
                for (int p = 0; p < 4; p++) fma2(dot[v][p], cpair[p], zd[v]);
        }
#pragma unroll
        for (int p = 0; p < 4; p++) {
            int code0 = cbase + cg * 8 + 2 * p;
            float cn0 = g_cnorm[code0], cn1 = g_cnorm[code0 + 1];
#pragma unroll
            for (int v = 0; v < 4; v++) {
                float2 dv = unpack2(dot[v][p]);
                float d0 = fmaf(-2.f, dv.x, cn0), d1 = fmaf(-2.f, dv.y, cn1);
                if (d0 < minv[v]) { minv[v] = d0; mini[v] = code0; }
                if (d1 < minv[v]) { minv[v] = d1; mini[v] = code0 + 1; }
                dot[v][p] = 0;
            }
        }
    }
    __syncthreads();
    float* rd = c_s; int* ri = (int*)(c_s + 1024);
#pragma unroll
    for (int v = 0; v < 4; v++) {
        int vl = vg * 4 + v;
        rd[vl * 16 + cg] = minv[v]; ri[vl * 16 + cg] = mini[v];
    }
    __syncthreads();
    if (tid < 64) {
        float bd = rd[tid * 16]; int bi = ri[tid * 16];
        for (int g = 1; g < 16; g++) {
            float d2 = rd[tid * 16 + g]; int i2 = ri[tid * 16 + g];
            if (d2 < bd || (d2 == bd && i2 < bi)) { bd = d2; bi = i2; }
        }
        idx_s[tid] = bi;
        g_idx[v0 + tid] = bi;
    }
    __syncthreads();
    for (int i = tid; i < 8192; i += 256) {
        int d = i >> 6, vl = i & 63;
        zq[(b * DIM + d) * 4096 + s0 + vl] = __ldg(&emb[idx_s[vl] * DIM + d]);
    }
}

// deconv1 gather (unchanged)
__global__ __launch_bounds__(256) void deconv1_gather_kernel() {
    __shared__ int sidx[6][18];
    int n = blockIdx.z, p0 = blockIdx.y * 8, q0 = blockIdx.x * 32;
    int tid = threadIdx.x;
    int rb = p0 / 2 - 1, cb = q0 / 2 - 1;
    for (int i = tid; i < 108; i += 256) {
        int r = i / 18, c = i - r * 18;
        int rr = rb + r, cc = cb + c;
        sidx[r][c] = ((unsigned)rr < H2 && (unsigned)cc < H2)
                     ? g_idx[n * 4096 + rr * 64 + cc] : 512;
    }
    __syncthreads();
    int oc = tid & 127, half = tid >> 7;
    const float* Toc = g_T + oc;
#pragma unroll
    for (int s = 0; s < 4; s++) {
        int pl = half * 4 + s, p = p0 + pl;
        int a4 = (p & 1) * 4;
        int rl = (pl + (p & 1)) >> 1;
        const int* r0 = sidx[rl];
        const int* r1 = sidx[rl + 1];
        float* op = g_g + ((n * DIM + oc) * H1 + p) * H1 + q0;
        for (int jj = 0; jj < 32; jj += 4) {
            int cl = jj >> 1;
            int k00 = r0[cl], k01 = r0[cl + 1], k02 = r0[cl + 2], k03 = r0[cl + 3];
            int k10 = r1[cl], k11 = r1[cl + 1], k12 = r1[cl + 2], k13 = r1[cl + 3];
            float4 v;
            v.x = __ldg(&Toc[(k00 * 16 + a4)     * 128]) + __ldg(&Toc[(k01 * 16 + a4 + 2)  * 128])
                + __ldg(&Toc[(k10 * 16 + a4 + 8) * 128]) + __ldg(&Toc[(k11 * 16 + a4 + 10) * 128]);
            v.y = __ldg(&Toc[(k01 * 16 + a4 + 1) * 128]) + __ldg(&Toc[(k02 * 16 + a4 + 3)  * 128])
                + __ldg(&Toc[(k11 * 16 + a4 + 9) * 128]) + __ldg(&Toc[(k12 * 16 + a4 + 11) * 128]);
            v.z = __ldg(&Toc[(k01 * 16 + a4)     * 128]) + __ldg(&Toc[(k02 * 16 + a4 + 2)  * 128])
                + __ldg(&Toc[(k11 * 16 + a4 + 8) * 128]) + __ldg(&Toc[(k12 * 16 + a4 + 10) * 128]);
            v.w = __ldg(&Toc[(k02 * 16 + a4 + 1) * 128]) + __ldg(&Toc[(k03 * 16 + a4 + 3)  * 128])
                + __ldg(&Toc[(k12 * 16 + a4 + 9) * 128]) + __ldg(&Toc[(k13 * 16 + a4 + 11) * 128]);
            v.x = fmaxf(v.x, 0.f); v.y = fmaxf(v.y, 0.f);
            v.z = fmaxf(v.z, 0.f); v.w = fmaxf(v.w, 0.f);
            *(float4*)(op + jj) = v;
        }
    }
}

// deconv2: pre-duplicated weights cp.async'd from g_W2; 32p x 32q tile.
#define D2_SMEM (CIN * 2048 * 8 + 2 * 2880 * 4)

__global__ __launch_bounds__(256) void deconv2_kernel(float* __restrict__ recon) {
    extern __shared__ u64 sd2[];
    u64* wsp2 = sd2;
    float* insb = (float*)(sd2 + CIN * 2048);
    int n = blockIdx.z;
    int p0 = blockIdx.y * 32, q0 = blockIdx.x * 32;
    int tid = threadIdx.x, pl = tid >> 4, qi = tid & 15;
    int qp = qi & 1, jj = qi >> 1, a = pl & 1;
    int r0l = (pl + a) >> 1, c0l = qp + 2 * jj;
    int rb = p0 / 2 - 1, cb = q0 / 2 - 1;

    u32 wsmem = cvta_s(wsp2);
#pragma unroll
    for (int j = 0; j < 12; j++) {
        int i = tid + j * 256;
        cp16(wsmem + i * 16, (const char*)g_W2 + i * 16);
    }
    for (int i = tid; i < 2592; i += 256) {
        int ic = i / 324, rem = i - ic * 324, r = rem / 18, c = rem - r * 18;
        int rr = rb + r, cc = cb + c;
        bool ok = ((unsigned)rr < H1) && ((unsigned)cc < H1);
        const float* src = ok ? &g_g[((n * DIM + ic) * H1 + rr) * H1 + cc] : g_g;
        cp4z(cvta_s(insb + ic * 360 + r * 20 + c), src, ok ? 4 : 0);
    }
    CP_COMMIT();

    u64 acc[2][3] = {{0, 0, 0}, {0, 0, 0}};
    for (int s = 0; s < 16; s++) {
        CP_WAIT0();
        __syncthreads();
        if (s < 15) {
            int ic0 = (s + 1) * 8;
            float* nb = insb + ((s + 1) & 1) * 2880;
            for (int i = tid; i < 2592; i += 256) {
                int ic = i / 324, rem = i - ic * 324, r = rem / 18, c = rem - r * 18;
                int rr = rb + r, cc = cb + c;
                bool ok = ((unsigned)rr < H1) && ((unsigned)cc < H1);
                const float* src = ok ? &g_g[((n * DIM + ic0 + ic) * H1 + rr) * H1 + cc] : g_g;
                cp4z(cvta_s(nb + ic * 360 + r * 20 + c), src, ok ? 4 : 0);
            }
            CP_COMMIT();
        }
        const float* buf = insb + (s & 1) * 2880;
        int ic0 = s * 8;
#pragma unroll
        for (int icl = 0; icl < 8; icl++) {
            const float* rpa = buf + icl * 360 + r0l * 20;
            const float* rpb = rpa + 160;
            float t00 = rpa[c0l], t01 = rpa[c0l + 1], t02 = rpa[c0l + 2];
            float t10 = rpa[20 + c0l], t11 = rpa[20 + c0l + 1], t12 = rpa[20 + c0l + 2];
            float u00 = rpb[c0l], u01 = rpb[c0l + 1], u02 = rpb[c0l + 2];
            float u10 = rpb[20 + c0l], u11 = rpb[20 + c0l + 1], u12 = rpb[20 + c0l + 2];
            u64 i0a = pack2(t00, t01), i0b = pack2(t01, t02);
            u64 i1a = pack2(t10, t11), i1b = pack2(t11, t12);
            u64 j0a = pack2(u00, u01), j0b = pack2(u01, u02);
            u64 j1a = pack2(u10, u11), j1b = pack2(u11, u12);
            int kb = (ic0 + icl) * 16 + (a * 2 + qp) * 4;
#pragma unroll
            for (int o = 0; o < 3; o++) {
                const ulonglong2* wq = (const ulonglong2*)(wsp2 + o * 2048 + kb);
                ulonglong2 w01 = wq[0], w23 = wq[1];
                fma2(acc[0][o], i0a, w01.x); fma2(acc[0][o], i0b, w01.y);
                fma2(acc[0][o], i1a, w23.x); fma2(acc[0][o], i1b, w23.y);
                fma2(acc[1][o], j0a, w01.x); fma2(acc[1][o], j0b, w01.y);
                fma2(acc[1][o], j1a, w23.x); fma2(acc[1][o], j1b, w23.y);
            }
        }
    }
    int q = q0 + qp + 4 * jj;
#pragma unroll
    for (int h = 0; h < 2; h++) {
        int p = p0 + pl + h * 16;
#pragma unroll
        for (int o = 0; o < 3; o++) {
            float2 v = unpack2(acc[h][o]);
            float* op = recon + ((n * CIN + o) * H0 + p) * H0;
            op[q] = tanhf(v.x);
            op[q + 2] = tanhf(v.y);
        }
    }
}

#define VQ_SMEM ((128 * 68 + 128 * 132) * (int)sizeof(float))

extern "C" void kernel_launch(void* const* d_in, const int* in_sizes, int n_in,
                              void* d_out, int out_size) {
    const float* x    = (const float*)d_in[0];
    const float* w_e1 = (const float*)d_in[1];
    const float* w_e2 = (const float*)d_in[2];
    const float* emb  = (const float*)d_in[3];
    const float* w_d1 = (const float*)d_in[4];
    const float* w_d2 = (const float*)d_in[5];
    float* out = (float*)d_out;
    float* recon = out;
    float* ze = out + OFF_ZE;
    float* zq = out + OFF_ZQ;

    cudaFuncSetAttribute(vq_kernel, cudaFuncAttributeMaxDynamicSharedMemorySize, VQ_SMEM);
    cudaFuncSetAttribute(conv2_kernel, cudaFuncAttributeMaxDynamicSharedMemorySize, C2_SMEM);
    cudaFuncSetAttribute(deconv2_kernel, cudaFuncAttributeMaxDynamicSharedMemorySize, D2_SMEM);

    knorm_kernel<<<2, 256>>>(emb);
    wd2dup_kernel<<<24, 256>>>(w_d2);
    tmat_kernel<<<128, 256>>>(emb, w_d1);
    conv1_kernel<<<dim3(64, B), 256>>>(x, w_e1);
    conv2_kernel<<<dim3(8, 8, B), 256, C2_SMEM>>>(w_e2, ze);
    vq_kernel<<<1024, 256, VQ_SMEM>>>(ze, emb, zq);
    deconv1_gather_kernel<<<dim3(4, 16, B), 256>>>();
    deconv2_kernel<<<dim3(8, 8, B), 256, D2_SMEM>>>(recon);
}

// round 16
// speedup vs baseline: 1.0988x; 1.0988x over previous
#include <cuda_runtime.h>
#include <math.h>

#define B 16
#define CIN 3
#define DIM 128
#define KCODES 512
#define H0 256
#define H1 128
#define H2 64
#define OFF_ZE  (B*CIN*H0*H0)
#define OFF_ZQ  (OFF_ZE + B*DIM*H2*H2)

__device__ float g_h[B*DIM*H1*H1];
__device__ float g_g[B*DIM*H1*H1];
__device__ float g_cnorm[KCODES];
__device__ int   g_idx[B*H2*H2];
__device__ float g_T[513*16*128];

typedef unsigned long long u64;
typedef unsigned int u32;
__device__ __forceinline__ void fma2(u64& d, u64 a, u64 b) {
    asm("fma.rn.f32x2 %0, %1, %2, %0;" : "+l"(d) : "l"(a), "l"(b));
}
__device__ __forceinline__ u64 pack2(float lo, float hi) {
    u64 r; asm("mov.b64 %0, {%1, %2};" : "=l"(r) : "f"(lo), "f"(hi)); return r;
}
__device__ __forceinline__ float2 unpack2(u64 v) {
    float2 r; asm("mov.b64 {%0, %1}, %2;" : "=f"(r.x), "=f"(r.y) : "l"(v)); return r;
}
__device__ __forceinline__ u64 lds2(const float* p) { return *(const u64*)p; }
__device__ __forceinline__ u32 cvta_s(const void* p) {
    u32 a; asm("{.reg .u64 t; cvta.to.shared.u64 t, %1; cvt.u32.u64 %0, t;}" : "=r"(a) : "l"(p));
    return a;
}
__device__ __forceinline__ void cp16(u32 d, const void* s) {
    asm volatile("cp.async.ca.shared.global [%0], [%1], 16;" :: "r"(d), "l"(s));
}
__device__ __forceinline__ void cp4z(u32 d, const void* s, int sz) {
    asm volatile("cp.async.ca.shared.global [%0], [%1], 4, %2;" :: "r"(d), "l"(s), "r"(sz));
}
#define CP_COMMIT() asm volatile("cp.async.commit_group;" ::: "memory")
#define CP_WAIT0()  asm volatile("cp.async.wait_group 0;" ::: "memory")

__global__ void knorm_kernel(const float* __restrict__ emb) {
    int k = blockIdx.x * blockDim.x + threadIdx.x;
    if (k < KCODES) {
        const float* e = emb + k * DIM;
        float s = 0.f;
#pragma unroll 8
        for (int d = 0; d < DIM; d++) s += e[d] * e[d];
        g_cnorm[k] = s;
    }
}

__global__ __launch_bounds__(256) void tmat_kernel(
    const float* __restrict__ emb, const float* __restrict__ wd1) {
    __shared__ float ws[2048];
    int oc = blockIdx.x, tid = threadIdx.x;
    for (int i = tid; i < 2048; i += 256) ws[i] = wd1[oc * 2048 + i];
    __syncthreads();
    for (int k = tid; k < 513; k += 256) {
        float acc[16];
#pragma unroll
        for (int t = 0; t < 16; t++) acc[t] = 0.f;
        if (k < 512) {
            const float* e = emb + k * DIM;
            for (int ic = 0; ic < 128; ic++) {
                float ev = __ldg(e + ic);
                const float* wp = &ws[ic * 16];
#pragma unroll
                for (int t = 0; t < 16; t++) acc[t] += ev * wp[t];
            }
        }
#pragma unroll
        for (int t = 0; t < 16; t++) g_T[(k * 16 + t) * 128 + oc] = acc[t];
    }
}

// conv1: contiguous 4-output groups, LDS.128 input loads. Chains bitwise-same.
__global__ __launch_bounds__(256) void conv1_kernel(
    const float* __restrict__ x, const float* __restrict__ w) {
    __shared__ float ws[DIM * 48];
    __shared__ float ins[CIN][6][260];
    int n = blockIdx.y, oy0 = blockIdx.x * 2, tid = threadIdx.x;
    for (int i = tid; i < DIM * 48; i += 256) ws[i] = w[i];
    int iyb = oy0 * 2 - 1;
    for (int i = tid; i < CIN * 6 * 258; i += 256) {
        int ic = i / 1548, rem = i - ic * 1548, r = rem / 258, c = rem - r * 258;
        int iy = iyb + r, ix = c - 1;
        float v = 0.f;
        if ((unsigned)iy < H0 && (unsigned)ix < H0) v = x[((n * CIN + ic) * H0 + iy) * H0 + ix];
        ins[ic][r][c] = v;
    }
    __syncthreads();
    int oc = tid >> 1, half = tid & 1;
    u64 wp[24];
#pragma unroll
    for (int ic = 0; ic < 3; ic++)
#pragma unroll
        for (int kh = 0; kh < 4; kh++) {
            const float* wk = &ws[oc * 48 + ic * 16 + kh * 4];
            wp[(ic * 4 + kh) * 2] = pack2(wk[0], wk[1]);
            wp[(ic * 4 + kh) * 2 + 1] = pack2(wk[2], wk[3]);
        }
#pragma unroll
    for (int ry = 0; ry < 2; ry++) {
        float* outp = g_h + ((n * DIM + oc) * H1 + oy0 + ry) * H1;
        for (int k = 0; k < 64; k += 4) {
            int ox = half * 64 + k;
            u64 a0 = 0, a1 = 0, a2 = 0, a3 = 0;
#pragma unroll
            for (int ic = 0; ic < 3; ic++)
#pragma unroll
                for (int kh = 0; kh < 4; kh++) {
                    const float* rp = &ins[ic][2 * ry + kh][2 * ox];
                    ulonglong2 A = *(const ulonglong2*)rp;        // pairs P0,P1
                    ulonglong2 Bv = *(const ulonglong2*)(rp + 4); // pairs P2,P3
                    u64 P4 = lds2(rp + 8);
                    u64 w01 = wp[(ic * 4 + kh) * 2], w23 = wp[(ic * 4 + kh) * 2 + 1];
                    fma2(a0, A.x, w01);  fma2(a0, A.y, w23);
                    fma2(a1, A.y, w01);  fma2(a1, Bv.x, w23);
                    fma2(a2, Bv.x, w01); fma2(a2, Bv.y, w23);
                    fma2(a3, Bv.y, w01); fma2(a3, P4, w23);
                }
            float2 v0 = unpack2(a0), v1 = unpack2(a1), v2 = unpack2(a2), v3 = unpack2(a3);
            float4 ov;
            ov.x = fmaxf(v0.x + v0.y, 0.f);
            ov.y = fmaxf(v1.x + v1.y, 0.f);
            ov.z = fmaxf(v2.x + v2.y, 0.f);
            ov.w = fmaxf(v3.x + v3.y, 0.f);
            *(float4*)(outp + ox) = ov;
        }
    }
}

// conv2 (unchanged — at FFMA2 floor)
#define C2_TBL_F 3072
#define C2_WS_F  8704
#define C2_BUF_F (C2_WS_F + 1584)
#define C2_SMEM  ((C2_TBL_F + 2 * C2_BUF_F) * 4)

__global__ __launch_bounds__(256, 2) void conv2_kernel(
    const float* __restrict__ w, float* __restrict__ ze) {
    extern __shared__ float s2[];
    uint2* tbl = (uint2*)s2;
    float* bufs = s2 + C2_TBL_F;
    int tid = threadIdx.x;
    int n = blockIdx.z, oy0 = blockIdx.y * 8, ox0 = blockIdx.x * 8;
    int ocg = tid >> 3, oyl = tid & 7;
    int iyb = oy0 * 2 - 1, ixb = ox0 * 2 - 1;
    u32 sbase = cvta_s(bufs);

    uint2* myt = tbl + tid * 6;
#pragma unroll
    for (int j = 0; j < 6; j++) {
        int i = tid + j * 256;
        u32 gof = 0, sof = (u32)((C2_WS_F + 19) * 4);
        if (i < 1296) {
            int ic = i / 324, rem = i - ic * 324, r = rem / 18, c = rem - r * 18;
            int iy = iyb + r, ix = ixb + c;
            bool ok = ((unsigned)iy < H1) && ((unsigned)ix < H1);
            sof = (u32)((C2_WS_F + ic * 396 + r * 22 + c) * 4) | (ok ? 1u : 0u);
            if (ok) gof = (u32)(((n * DIM + ic) * H1 + iy) * H1 + ix);
        }
        myt[j] = make_uint2(gof, sof);
    }
    int woc0 = tid >> 4;
    u32 wdofs = (u32)(woc0 * 68 * 4 + (tid & 15) * 16);
    const float* wsrc = w + woc0 * 2048 + (tid & 15) * 4;

    u64 acc[4][8];
#pragma unroll
    for (int o = 0; o < 4; o++)
#pragma unroll
        for (int j = 0; j < 8; j++) acc[o][j] = 0;

    {
        u32 bb = sbase;
#pragma unroll
        for (int jj = 0; jj < 8; jj++)
            cp16(bb + wdofs + jj * (16 * 68 * 4), wsrc + jj * (16 * 2048));
#pragma unroll
        for (int jj = 0; jj < 5; jj++) {
            uint2 e = myt[jj];
            cp4z(bb + (e.y & ~1u), g_h + e.x, (e.y & 1) * 4);
        }
        if (tid < 16) {
            uint2 e = myt[5];
            cp4z(bb + (e.y & ~1u), g_h + e.x, (e.y & 1) * 4);
        }
    }
    CP_COMMIT();

    for (int st = 0; st < 32; st++) {
        CP_WAIT0();
        __syncthreads();
        if (st < 31) {
            u32 bb = sbase + ((st + 1) & 1) * (C2_BUF_F * 4);
            const float* wsp = wsrc + (st + 1) * 64;
            const float* gbase = g_h + (st + 1) * 65536;
#pragma unroll
            for (int jj = 0; jj < 8; jj++)
                cp16(bb + wdofs + jj * (16 * 68 * 4), wsp + jj * (16 * 2048));
#pragma unroll
            for (int jj = 0; jj < 5; jj++) {
                uint2 e = myt[jj];
                cp4z(bb + (e.y & ~1u), gbase + e.x, (e.y & 1) * 4);
            }
            if (tid < 16) {
                uint2 e = myt[5];
                cp4z(bb + (e.y & ~1u), gbase + e.x, (e.y & 1) * 4);
            }
            CP_COMMIT();
        }
        float* wsb = bufs + (st & 1) * C2_BUF_F;
        float* insb = wsb + C2_WS_F;
#pragma unroll
        for (int icl = 0; icl < 4; icl++) {
#pragma unroll
            for (int kh = 0; kh < 4; kh++) {
                const float* rp = insb + icl * 396 + (oyl * 2 + kh) * 22;
                u64 ivp[9];
#pragma unroll
                for (int m = 0; m < 9; m++) ivp[m] = lds2(rp + 2 * m);
#pragma unroll
                for (int o = 0; o < 4; o++) {
                    const ulonglong2* wpt = (const ulonglong2*)
                        (wsb + (ocg * 4 + o) * 68 + icl * 16 + kh * 4);
                    ulonglong2 wv = *wpt;
#pragma unroll
                    for (int j = 0; j < 8; j++) {
                        fma2(acc[o][j], ivp[j], wv.x);
                        fma2(acc[o][j], ivp[j + 1], wv.y);
                    }
                }
            }
        }
    }
    int oy = oy0 + oyl;
#pragma unroll
    for (int o = 0; o < 4; o++) {
        float* op = ze + ((n * DIM + ocg * 4 + o) * H2 + oy) * H2 + ox0;
#pragma unroll
        for (int j = 0; j < 8; j++) {
            float2 v = unpack2(acc[o][j]);
            op[j] = v.x + v.y;
        }
    }
}

// VQ (R14 version)
__global__ __launch_bounds__(256) void vq_kernel(
    const float* __restrict__ ze, const float* __restrict__ emb, float* __restrict__ zq) {
    extern __shared__ float sm[];
    float* z_s = sm;
    float* c_s = sm + 128 * 68;
    __shared__ int idx_s[64];
    int tid = threadIdx.x;
    int v0 = blockIdx.x * 64, b = v0 >> 12, s0 = v0 & 4095;
    for (int i = tid; i < 2048; i += 256) {
        int d = i >> 4, vl4 = (i & 15) * 4;
        *(float4*)&z_s[d * 68 + vl4] = *(const float4*)&ze[(b * DIM + d) * 4096 + s0 + vl4];
    }
    int vg = tid >> 4, cg = tid & 15;
    float minv[4]; int mini[4];
#pragma unroll
    for (int v = 0; v < 4; v++) { minv[v] = 3.0e38f; mini[v] = 0; }
    u64 dot[2][8];
#pragma unroll
    for (int vp = 0; vp < 2; vp++)
#pragma unroll
        for (int c = 0; c < 8; c++) dot[vp][c] = 0;
    for (int ch = 0; ch < 4; ch++) {
        __syncthreads();
        int cbase = ch * 128;
        for (int i = tid; i < 4096; i += 256) {
            int cl = i & 127, dq = (i >> 7) * 4;
            float4 t = *(const float4*)&emb[(cbase + cl) * DIM + dq];
            c_s[dq * 132 + cl] = t.x; c_s[(dq + 1) * 132 + cl] = t.y;
            c_s[(dq + 2) * 132 + cl] = t.z; c_s[(dq + 3) * 132 + cl] = t.w;
        }
        __syncthreads();
#pragma unroll 2
        for (int d = 0; d < 128; d++) {
            const float* zp = &z_s[d * 68 + vg * 4];
            float4 z0 = *(const float4*)zp;
            u64 zpk[2] = {pack2(z0.x, z0.y), pack2(z0.z, z0.w)};
            const float* cp = &c_s[d * 132];
            float4 c0 = *(const float4*)(cp + cg * 4), c1 = *(const float4*)(cp + 64 + cg * 4);
            u64 cb[8] = {pack2(c0.x, c0.x), pack2(c0.y, c0.y), pack2(c0.z, c0.z), pack2(c0.w, c0.w),
                         pack2(c1.x, c1.x), pack2(c1.y, c1.y), pack2(c1.z, c1.z), pack2(c1.w, c1.w)};
#pragma unroll
            for (int vp = 0; vp < 2; vp++)
#pragma unroll
                for (int c = 0; c < 8; c++) fma2(dot[vp][c], zpk[vp], cb[c]);
        }
#pragma unroll
        for (int c = 0; c < 8; c++) {
            int code = cbase + (c < 4 ? cg * 4 + c : 64 + cg * 4 + (c - 4));
            float cn = g_cnorm[code];
#pragma unroll
            for (int vp = 0; vp < 2; vp++) {
                float2 dv = unpack2(dot[vp][c]);
                float d0 = fmaf(-2.f, dv.x, cn), d1 = fmaf(-2.f, dv.y, cn);
                if (d0 < minv[2 * vp]) { minv[2 * vp] = d0; mini[2 * vp] = code; }
                if (d1 < minv[2 * vp + 1]) { minv[2 * vp + 1] = d1; mini[2 * vp + 1] = code; }
                dot[vp][c] = 0;
            }
        }
    }
    __syncthreads();
    float* rd = c_s; int* ri = (int*)(c_s + 1024);
#pragma unroll
    for (int v = 0; v < 4; v++) {
        int vl = vg * 4 + v;
        rd[vl * 16 + cg] = minv[v]; ri[vl * 16 + cg] = mini[v];
    }
    __syncthreads();
    if (tid < 64) {
        float bd = rd[tid * 16]; int bi = ri[tid * 16];
        for (int g = 1; g < 16; g++) {
            float d2 = rd[tid * 16 + g]; int i2 = ri[tid * 16 + g];
            if (d2 < bd || (d2 == bd && i2 < bi)) { bd = d2; bi = i2; }
        }
        idx_s[tid] = bi;
        g_idx[v0 + tid] = bi;
    }
    __syncthreads();
    for (int i = tid; i < 8192; i += 256) {
        int d = i >> 6, vl = i & 63;
        zq[(b * DIM + d) * 4096 + s0 + vl] = __ldg(&emb[idx_s[vl] * DIM + d]);
    }
}

// deconv1 gather (unchanged)
__global__ __launch_bounds__(256) void deconv1_gather_kernel() {
    __shared__ int sidx[6][18];
    int n = blockIdx.z, p0 = blockIdx.y * 8, q0 = blockIdx.x * 32;
    int tid = threadIdx.x;
    int rb = p0 / 2 - 1, cb = q0 / 2 - 1;
    for (int i = tid; i < 108; i += 256) {
        int r = i / 18, c = i - r * 18;
        int rr = rb + r, cc = cb + c;
        sidx[r][c] = ((unsigned)rr < H2 && (unsigned)cc < H2)
                     ? g_idx[n * 4096 + rr * 64 + cc] : 512;
    }
    __syncthreads();
    int oc = tid & 127, half = tid >> 7;
    const float* Toc = g_T + oc;
#pragma unroll
    for (int s = 0; s < 4; s++) {
        int pl = half * 4 + s, p = p0 + pl;
        int a4 = (p & 1) * 4;
        int rl = (pl + (p & 1)) >> 1;
        const int* r0 = sidx[rl];
        const int* r1 = sidx[rl + 1];
        float* op = g_g + ((n * DIM + oc) * H1 + p) * H1 + q0;
        for (int jj = 0; jj < 32; jj += 4) {
            int cl = jj >> 1;
            int k00 = r0[cl], k01 = r0[cl + 1], k02 = r0[cl + 2], k03 = r0[cl + 3];
            int k10 = r1[cl], k11 = r1[cl + 1], k12 = r1[cl + 2], k13 = r1[cl + 3];
            float4 v;
            v.x = __ldg(&Toc[(k00 * 16 + a4)     * 128]) + __ldg(&Toc[(k01 * 16 + a4 + 2)  * 128])
                + __ldg(&Toc[(k10 * 16 + a4 + 8) * 128]) + __ldg(&Toc[(k11 * 16 + a4 + 10) * 128]);
            v.y = __ldg(&Toc[(k01 * 16 + a4 + 1) * 128]) + __ldg(&Toc[(k02 * 16 + a4 + 3)  * 128])
                + __ldg(&Toc[(k11 * 16 + a4 + 9) * 128]) + __ldg(&Toc[(k12 * 16 + a4 + 11) * 128]);
            v.z = __ldg(&Toc[(k01 * 16 + a4)     * 128]) + __ldg(&Toc[(k02 * 16 + a4 + 2)  * 128])
                + __ldg(&Toc[(k11 * 16 + a4 + 8) * 128]) + __ldg(&Toc[(k12 * 16 + a4 + 10) * 128]);
            v.w = __ldg(&Toc[(k02 * 16 + a4 + 1) * 128]) + __ldg(&Toc[(k03 * 16 + a4 + 3)  * 128])
                + __ldg(&Toc[(k12 * 16 + a4 + 9) * 128]) + __ldg(&Toc[(k13 * 16 + a4 + 11) * 128]);
            v.x = fmaxf(v.x, 0.f); v.y = fmaxf(v.y, 0.f);
            v.z = fmaxf(v.z, 0.f); v.w = fmaxf(v.w, 0.f);
            *(float4*)(op + jj) = v;
        }
    }
}

// deconv2 (R14 version: static smem weights, 32p x 32q tile)
__global__ __launch_bounds__(256) void deconv2_kernel(
    const float* __restrict__ w, float* __restrict__ recon) {
    __shared__ float wsp[CIN * DIM * 16];
    __shared__ float insb[2][2880];
    int n = blockIdx.z;
    int p0 = blockIdx.y * 32, q0 = blockIdx.x * 32;
    int tid = threadIdx.x, pl = tid >> 4, qi = tid & 15;
    int qp = qi & 1, jj = qi >> 1, a = pl & 1;
    int r0l = (pl + a) >> 1, c0l = qp + 2 * jj;
    int rb = p0 / 2 - 1, cb = q0 / 2 - 1;
    for (int i = tid; i < CIN * DIM * 16; i += 256) {
        int oc = i >> 11, rem = i & 2047;
        int ic = rem >> 4, k = rem & 15, kh = k >> 2, kw = k & 3;
        int slot = ic * 16 + ((kh & 1) * 2 + (kw & 1)) * 4 + ((kh >> 1) << 1) + (kw >> 1);
        wsp[oc * 2048 + slot] = w[i];
    }
    for (int i = tid; i < 2592; i += 256) {
        int ic = i / 324, rem = i - ic * 324, r = rem / 18, c = rem - r * 18;
        int rr = rb + r, cc = cb + c;
        bool ok = ((unsigned)rr < H1) && ((unsigned)cc < H1);
        const float* src = ok ? &g_g[((n * DIM + ic) * H1 + rr) * H1 + cc] : g_g;
        cp4z(cvta_s(&insb[0][ic * 360 + r * 20 + c]), src, ok ? 4 : 0);
    }
    CP_COMMIT();

    u64 acc[2][3] = {{0, 0, 0}, {0, 0, 0}};
    for (int s = 0; s < 16; s++) {
        CP_WAIT0();
        __syncthreads();
        if (s < 15) {
            int ic0 = (s + 1) * 8;
            float* nb = insb[(s + 1) & 1];
            for (int i = tid; i < 2592; i += 256) {
                int ic = i / 324, rem = i - ic * 324, r = rem / 18, c = rem - r * 18;
                int rr = rb + r, cc = cb + c;
                bool ok = ((unsigned)rr < H1) && ((unsigned)cc < H1);
                const float* src = ok ? &g_g[((n * DIM + ic0 + ic) * H1 + rr) * H1 + cc] : g_g;
                cp4z(cvta_s(nb + ic * 360 + r * 20 + c), src, ok ? 4 : 0);
            }
            CP_COMMIT();
        }
        const float* buf = insb[s & 1];
        int ic0 = s * 8;
#pragma unroll
        for (int icl = 0; icl < 8; icl++) {
            const float* rpa = buf + icl * 360 + r0l * 20;
            const float* rpb = rpa + 160;
            float t00 = rpa[c0l], t01 = rpa[c0l + 1], t02 = rpa[c0l + 2];
            float t10 = rpa[20 + c0l], t11 = rpa[20 + c0l + 1], t12 = rpa[20 + c0l + 2];
            float u00 = rpb[c0l], u01 = rpb[c0l + 1], u02 = rpb[c0l + 2];
            float u10 = rpb[20 + c0l], u11 = rpb[20 + c0l + 1], u12 = rpb[20 + c0l + 2];
            u64 i0a = pack2(t00, t01), i0b = pack2(t01, t02);
            u64 i1a = pack2(t10, t11), i1b = pack2(t11, t12);
            u64 j0a = pack2(u00, u01), j0b = pack2(u01, u02);
            u64 j1a = pack2(u10, u11), j1b = pack2(u11, u12);
            int kb = (ic0 + icl) * 16 + (a * 2 + qp) * 4;
#pragma unroll
            for (int o = 0; o < 3; o++) {
                float4 wg = *(const float4*)&wsp[o * 2048 + kb];
                u64 wx = pack2(wg.x, wg.x), wy = pack2(wg.y, wg.y);
                u64 wz = pack2(wg.z, wg.z), ww = pack2(wg.w, wg.w);
                fma2(acc[0][o], i0a, wx); fma2(acc[0][o], i0b, wy);
                fma2(acc[0][o], i1a, wz); fma2(acc[0][o], i1b, ww);
                fma2(acc[1][o], j0a, wx); fma2(acc[1][o], j0b, wy);
                fma2(acc[1][o], j1a, wz); fma2(acc[1][o], j1b, ww);
            }
        }
    }
    int q = q0 + qp + 4 * jj;
#pragma unroll
    for (int h = 0; h < 2; h++) {
        int p = p0 + pl + h * 16;
#pragma unroll
        for (int o = 0; o < 3; o++) {
            float2 v = unpack2(acc[h][o]);
            float* op = recon + ((n * CIN + o) * H0 + p) * H0;
            op[q] = tanhf(v.x);
            op[q + 2] = tanhf(v.y);
        }
    }
}

#define VQ_SMEM ((128 * 68 + 128 * 132) * (int)sizeof(float))

extern "C" void kernel_launch(void* const* d_in, const int* in_sizes, int n_in,
                              void* d_out, int out_size) {
    const float* x    = (const float*)d_in[0];
    const float* w_e1 = (const float*)d_in[1];
    const float* w_e2 = (const float*)d_in[2];
    const float* emb  = (const float*)d_in[3];
    const float* w_d1 = (const float*)d_in[4];
    const float* w_d2 = (const float*)d_in[5];
    float* out = (float*)d_out;
    float* recon = out;
    float* ze = out + OFF_ZE;
    float* zq = out + OFF_ZQ;

    cudaFuncSetAttribute(vq_kernel, cudaFuncAttributeMaxDynamicSharedMemorySize, VQ_SMEM);
    cudaFuncSetAttribute(conv2_kernel, cudaFuncAttributeMaxDynamicSharedMemorySize, C2_SMEM);

    knorm_kernel<<<2, 256>>>(emb);
    tmat_kernel<<<128, 256>>>(emb, w_d1);
    conv1_kernel<<<dim3(64, B), 256>>>(x, w_e1);
    conv2_kernel<<<dim3(8, 8, B), 256, C2_SMEM>>>(w_e2, ze);
    vq_kernel<<<1024, 256, VQ_SMEM>>>(ze, emb, zq);
    deconv1_gather_kernel<<<dim3(4, 16, B), 256>>>();
    deconv2_kernel<<<dim3(8, 8, B), 256>>>(w_d2, recon);
}

// round 17
// speedup vs baseline: 1.1054x; 1.0061x over previous
#include <cuda_runtime.h>
#include <math.h>

#define B 16
#define CIN 3
#define DIM 128
#define KCODES 512
#define H0 256
#define H1 128
#define H2 64
#define OFF_ZE  (B*CIN*H0*H0)
#define OFF_ZQ  (OFF_ZE + B*DIM*H2*H2)

__device__ float g_h[B*DIM*H1*H1];
__device__ float g_g[B*DIM*H1*H1];
__device__ float g_cnorm[KCODES];
__device__ int   g_idx[B*H2*H2];
__device__ float g_T[513*16*128];

typedef unsigned long long u64;
typedef unsigned int u32;
__device__ __forceinline__ void fma2(u64& d, u64 a, u64 b) {
    asm("fma.rn.f32x2 %0, %1, %2, %0;" : "+l"(d) : "l"(a), "l"(b));
}
__device__ __forceinline__ u64 pack2(float lo, float hi) {
    u64 r; asm("mov.b64 %0, {%1, %2};" : "=l"(r) : "f"(lo), "f"(hi)); return r;
}
__device__ __forceinline__ float2 unpack2(u64 v) {
    float2 r; asm("mov.b64 {%0, %1}, %2;" : "=f"(r.x), "=f"(r.y) : "l"(v)); return r;
}
__device__ __forceinline__ u64 lds2(const float* p) { return *(const u64*)p; }
__device__ __forceinline__ u32 cvta_s(const void* p) {
    u32 a; asm("{.reg .u64 t; cvta.to.shared.u64 t, %1; cvt.u32.u64 %0, t;}" : "=r"(a) : "l"(p));
    return a;
}
__device__ __forceinline__ void cp16(u32 d, const void* s) {
    asm volatile("cp.async.ca.shared.global [%0], [%1], 16;" :: "r"(d), "l"(s));
}
__device__ __forceinline__ void cp4z(u32 d, const void* s, int sz) {
    asm volatile("cp.async.ca.shared.global [%0], [%1], 4, %2;" :: "r"(d), "l"(s), "r"(sz));
}
#define CP_COMMIT() asm volatile("cp.async.commit_group;" ::: "memory")
#define CP_WAIT0()  asm volatile("cp.async.wait_group 0;" ::: "memory")

__global__ void knorm_kernel(const float* __restrict__ emb) {
    int k = blockIdx.x * blockDim.x + threadIdx.x;
    if (k < KCODES) {
        const float* e = emb + k * DIM;
        float s = 0.f;
#pragma unroll 8
        for (int d = 0; d < DIM; d++) s += e[d] * e[d];
        g_cnorm[k] = s;
    }
}

__global__ __launch_bounds__(256) void tmat_kernel(
    const float* __restrict__ emb, const float* __restrict__ wd1) {
    __shared__ float ws[2048];
    int oc = blockIdx.x, tid = threadIdx.x;
    for (int i = tid; i < 2048; i += 256) ws[i] = wd1[oc * 2048 + i];
    __syncthreads();
    for (int k = tid; k < 513; k += 256) {
        float acc[16];
#pragma unroll
        for (int t = 0; t < 16; t++) acc[t] = 0.f;
        if (k < 512) {
            const float* e = emb + k * DIM;
            for (int ic = 0; ic < 128; ic++) {
                float ev = __ldg(e + ic);
                const float* wp = &ws[ic * 16];
#pragma unroll
                for (int t = 0; t < 16; t++) acc[t] += ev * wp[t];
            }
        }
#pragma unroll
        for (int t = 0; t < 16; t++) g_T[(k * 16 + t) * 128 + oc] = acc[t];
    }
}

// conv1 (R16 version)
__global__ __launch_bounds__(256) void conv1_kernel(
    const float* __restrict__ x, const float* __restrict__ w) {
    __shared__ float ws[DIM * 48];
    __shared__ float ins[CIN][6][260];
    int n = blockIdx.y, oy0 = blockIdx.x * 2, tid = threadIdx.x;
    for (int i = tid; i < DIM * 48; i += 256) ws[i] = w[i];
    int iyb = oy0 * 2 - 1;
    for (int i = tid; i < CIN * 6 * 258; i += 256) {
        int ic = i / 1548, rem = i - ic * 1548, r = rem / 258, c = rem - r * 258;
        int iy = iyb + r, ix = c - 1;
        float v = 0.f;
        if ((unsigned)iy < H0 && (unsigned)ix < H0) v = x[((n * CIN + ic) * H0 + iy) * H0 + ix];
        ins[ic][r][c] = v;
    }
    __syncthreads();
    int oc = tid >> 1, half = tid & 1;
    u64 wp[24];
#pragma unroll
    for (int ic = 0; ic < 3; ic++)
#pragma unroll
        for (int kh = 0; kh < 4; kh++) {
            const float* wk = &ws[oc * 48 + ic * 16 + kh * 4];
            wp[(ic * 4 + kh) * 2] = pack2(wk[0], wk[1]);
            wp[(ic * 4 + kh) * 2 + 1] = pack2(wk[2], wk[3]);
        }
#pragma unroll
    for (int ry = 0; ry < 2; ry++) {
        float* outp = g_h + ((n * DIM + oc) * H1 + oy0 + ry) * H1;
        for (int k = 0; k < 64; k += 4) {
            int ox = half * 64 + k;
            u64 a0 = 0, a1 = 0, a2 = 0, a3 = 0;
#pragma unroll
            for (int ic = 0; ic < 3; ic++)
#pragma unroll
                for (int kh = 0; kh < 4; kh++) {
                    const float* rp = &ins[ic][2 * ry + kh][2 * ox];
                    ulonglong2 A = *(const ulonglong2*)rp;
                    ulonglong2 Bv = *(const ulonglong2*)(rp + 4);
                    u64 P4 = lds2(rp + 8);
                    u64 w01 = wp[(ic * 4 + kh) * 2], w23 = wp[(ic * 4 + kh) * 2 + 1];
                    fma2(a0, A.x, w01);  fma2(a0, A.y, w23);
                    fma2(a1, A.y, w01);  fma2(a1, Bv.x, w23);
                    fma2(a2, Bv.x, w01); fma2(a2, Bv.y, w23);
                    fma2(a3, Bv.y, w01); fma2(a3, P4, w23);
                }
            float2 v0 = unpack2(a0), v1 = unpack2(a1), v2 = unpack2(a2), v3 = unpack2(a3);
            float4 ov;
            ov.x = fmaxf(v0.x + v0.y, 0.f);
            ov.y = fmaxf(v1.x + v1.y, 0.f);
            ov.z = fmaxf(v2.x + v2.y, 0.f);
            ov.w = fmaxf(v3.x + v3.y, 0.f);
            *(float4*)(outp + ox) = ov;
        }
    }
}

// conv2 (unchanged — at FFMA2 floor)
#define C2_TBL_F 3072
#define C2_WS_F  8704
#define C2_BUF_F (C2_WS_F + 1584)
#define C2_SMEM  ((C2_TBL_F + 2 * C2_BUF_F) * 4)

__global__ __launch_bounds__(256, 2) void conv2_kernel(
    const float* __restrict__ w, float* __restrict__ ze) {
    extern __shared__ float s2[];
    uint2* tbl = (uint2*)s2;
    float* bufs = s2 + C2_TBL_F;
    int tid = threadIdx.x;
    int n = blockIdx.z, oy0 = blockIdx.y * 8, ox0 = blockIdx.x * 8;
    int ocg = tid >> 3, oyl = tid & 7;
    int iyb = oy0 * 2 - 1, ixb = ox0 * 2 - 1;
    u32 sbase = cvta_s(bufs);

    uint2* myt = tbl + tid * 6;
#pragma unroll
    for (int j = 0; j < 6; j++) {
        int i = tid + j * 256;
        u32 gof = 0, sof = (u32)((C2_WS_F + 19) * 4);
        if (i < 1296) {
            int ic = i / 324, rem = i - ic * 324, r = rem / 18, c = rem - r * 18;
            int iy = iyb + r, ix = ixb + c;
            bool ok = ((unsigned)iy < H1) && ((unsigned)ix < H1);
            sof = (u32)((C2_WS_F + ic * 396 + r * 22 + c) * 4) | (ok ? 1u : 0u);
            if (ok) gof = (u32)(((n * DIM + ic) * H1 + iy) * H1 + ix);
        }
        myt[j] = make_uint2(gof, sof);
    }
    int woc0 = tid >> 4;
    u32 wdofs = (u32)(woc0 * 68 * 4 + (tid & 15) * 16);
    const float* wsrc = w + woc0 * 2048 + (tid & 15) * 4;

    u64 acc[4][8];
#pragma unroll
    for (int o = 0; o < 4; o++)
#pragma unroll
        for (int j = 0; j < 8; j++) acc[o][j] = 0;

    {
        u32 bb = sbase;
#pragma unroll
        for (int jj = 0; jj < 8; jj++)
            cp16(bb + wdofs + jj * (16 * 68 * 4), wsrc + jj * (16 * 2048));
#pragma unroll
        for (int jj = 0; jj < 5; jj++) {
            uint2 e = myt[jj];
            cp4z(bb + (e.y & ~1u), g_h + e.x, (e.y & 1) * 4);
        }
        if (tid < 16) {
            uint2 e = myt[5];
            cp4z(bb + (e.y & ~1u), g_h + e.x, (e.y & 1) * 4);
        }
    }
    CP_COMMIT();

    for (int st = 0; st < 32; st++) {
        CP_WAIT0();
        __syncthreads();
        if (st < 31) {
            u32 bb = sbase + ((st + 1) & 1) * (C2_BUF_F * 4);
            const float* wsp = wsrc + (st + 1) * 64;
            const float* gbase = g_h + (st + 1) * 65536;
#pragma unroll
            for (int jj = 0; jj < 8; jj++)
                cp16(bb + wdofs + jj * (16 * 68 * 4), wsp + jj * (16 * 2048));
#pragma unroll
            for (int jj = 0; jj < 5; jj++) {
                uint2 e = myt[jj];
                cp4z(bb + (e.y & ~1u), gbase + e.x, (e.y & 1) * 4);
            }
            if (tid < 16) {
                uint2 e = myt[5];
                cp4z(bb + (e.y & ~1u), gbase + e.x, (e.y & 1) * 4);
            }
            CP_COMMIT();
        }
        float* wsb = bufs + (st & 1) * C2_BUF_F;
        float* insb = wsb + C2_WS_F;
#pragma unroll
        for (int icl = 0; icl < 4; icl++) {
#pragma unroll
            for (int kh = 0; kh < 4; kh++) {
                const float* rp = insb + icl * 396 + (oyl * 2 + kh) * 22;
                u64 ivp[9];
#pragma unroll
                for (int m = 0; m < 9; m++) ivp[m] = lds2(rp + 2 * m);
#pragma unroll
                for (int o = 0; o < 4; o++) {
                    const ulonglong2* wpt = (const ulonglong2*)
                        (wsb + (ocg * 4 + o) * 68 + icl * 16 + kh * 4);
                    ulonglong2 wv = *wpt;
#pragma unroll
                    for (int j = 0; j < 8; j++) {
                        fma2(acc[o][j], ivp[j], wv.x);
                        fma2(acc[o][j], ivp[j + 1], wv.y);
                    }
                }
            }
        }
    }
    int oy = oy0 + oyl;
#pragma unroll
    for (int o = 0; o < 4; o++) {
        float* op = ze + ((n * DIM + ocg * 4 + o) * H2 + oy) * H2 + ox0;
#pragma unroll
        for (int j = 0; j < 8; j++) {
            float2 v = unpack2(acc[o][j]);
            op[j] = v.x + v.y;
        }
    }
}

// VQ: R16 distance path + coalesced two-phase gather (bitwise-same zq).
__global__ __launch_bounds__(256) void vq_kernel(
    const float* __restrict__ ze, const float* __restrict__ emb, float* __restrict__ zq) {
    extern __shared__ float sm[];
    float* z_s = sm;
    float* c_s = sm + 128 * 68;
    __shared__ int idx_s[64];
    int tid = threadIdx.x;
    int v0 = blockIdx.x * 64, b = v0 >> 12, s0 = v0 & 4095;
    for (int i = tid; i < 2048; i += 256) {
        int d = i >> 4, vl4 = (i & 15) * 4;
        *(float4*)&z_s[d * 68 + vl4] = *(const float4*)&ze[(b * DIM + d) * 4096 + s0 + vl4];
    }
    int vg = tid >> 4, cg = tid & 15;
    float minv[4]; int mini[4];
#pragma unroll
    for (int v = 0; v < 4; v++) { minv[v] = 3.0e38f; mini[v] = 0; }
    u64 dot[2][8];
#pragma unroll
    for (int vp = 0; vp < 2; vp++)
#pragma unroll
        for (int c = 0; c < 8; c++) dot[vp][c] = 0;
    for (int ch = 0; ch < 4; ch++) {
        __syncthreads();
        int cbase = ch * 128;
        for (int i = tid; i < 4096; i += 256) {
            int cl = i & 127, dq = (i >> 7) * 4;
            float4 t = *(const float4*)&emb[(cbase + cl) * DIM + dq];
            c_s[dq * 132 + cl] = t.x; c_s[(dq + 1) * 132 + cl] = t.y;
            c_s[(dq + 2) * 132 + cl] = t.z; c_s[(dq + 3) * 132 + cl] = t.w;
        }
        __syncthreads();
#pragma unroll 2
        for (int d = 0; d < 128; d++) {
            const float* zp = &z_s[d * 68 + vg * 4];
            float4 z0 = *(const float4*)zp;
            u64 zpk[2] = {pack2(z0.x, z0.y), pack2(z0.z, z0.w)};
            const float* cp = &c_s[d * 132];
            float4 c0 = *(const float4*)(cp + cg * 4), c1 = *(const float4*)(cp + 64 + cg * 4);
            u64 cb[8] = {pack2(c0.x, c0.x), pack2(c0.y, c0.y), pack2(c0.z, c0.z), pack2(c0.w, c0.w),
                         pack2(c1.x, c1.x), pack2(c1.y, c1.y), pack2(c1.z, c1.z), pack2(c1.w, c1.w)};
#pragma unroll
            for (int vp = 0; vp < 2; vp++)
#pragma unroll
                for (int c = 0; c < 8; c++) fma2(dot[vp][c], zpk[vp], cb[c]);
        }
#pragma unroll
        for (int c = 0; c < 8; c++) {
            int code = cbase + (c < 4 ? cg * 4 + c : 64 + cg * 4 + (c - 4));
            float cn = g_cnorm[code];
#pragma unroll
            for (int vp = 0; vp < 2; vp++) {
                float2 dv = unpack2(dot[vp][c]);
                float d0 = fmaf(-2.f, dv.x, cn), d1 = fmaf(-2.f, dv.y, cn);
                if (d0 < minv[2 * vp]) { minv[2 * vp] = d0; mini[2 * vp] = code; }
                if (d1 < minv[2 * vp + 1]) { minv[2 * vp + 1] = d1; mini[2 * vp + 1] = code; }
                dot[vp][c] = 0;
            }
        }
    }
    __syncthreads();
    float* rd = c_s; int* ri = (int*)(c_s + 1024);
#pragma unroll
    for (int v = 0; v < 4; v++) {
        int vl = vg * 4 + v;
        rd[vl * 16 + cg] = minv[v]; ri[vl * 16 + cg] = mini[v];
    }
    __syncthreads();
    if (tid < 64) {
        float bd = rd[tid * 16]; int bi = ri[tid * 16];
        for (int g = 1; g < 16; g++) {
            float d2 = rd[tid * 16 + g]; int i2 = ri[tid * 16 + g];
            if (d2 < bd || (d2 == bd && i2 < bi)) { bd = d2; bi = i2; }
        }
        idx_s[tid] = bi;
        g_idx[v0 + tid] = bi;
    }
    __syncthreads();
    // phase 1: coalesced row reads into pitch-65 smem tile
    float* zs2 = c_s;   // 128*65 = 8320 floats <= 128*132
    for (int i = tid; i < 2048; i += 256) {
        int vl = i >> 5, d4 = (i & 31) * 4;
        float4 t = *(const float4*)&emb[idx_s[vl] * DIM + d4];
        zs2[(d4 + 0) * 65 + vl] = t.x;
        zs2[(d4 + 1) * 65 + vl] = t.y;
        zs2[(d4 + 2) * 65 + vl] = t.z;
        zs2[(d4 + 3) * 65 + vl] = t.w;
    }
    __syncthreads();
    // phase 2: coalesced writes (same order/values as before)
    for (int i = tid; i < 8192; i += 256) {
        int d = i >> 6, vl = i & 63;
        zq[(b * DIM + d) * 4096 + s0 + vl] = zs2[d * 65 + vl];
    }
}

// deconv1 gather (unchanged)
__global__ __launch_bounds__(256) void deconv1_gather_kernel() {
    __shared__ int sidx[6][18];
    int n = blockIdx.z, p0 = blockIdx.y * 8, q0 = blockIdx.x * 32;
    int tid = threadIdx.x;
    int rb = p0 / 2 - 1, cb = q0 / 2 - 1;
    for (int i = tid; i < 108; i += 256) {
        int r = i / 18, c = i - r * 18;
        int rr = rb + r, cc = cb + c;
        sidx[r][c] = ((unsigned)rr < H2 && (unsigned)cc < H2)
                     ? g_idx[n * 4096 + rr * 64 + cc] : 512;
    }
    __syncthreads();
    int oc = tid & 127, half = tid >> 7;
    const float* Toc = g_T + oc;
#pragma unroll
    for (int s = 0; s < 4; s++) {
        int pl = half * 4 + s, p = p0 + pl;
        int a4 = (p & 1) * 4;
        int rl = (pl + (p & 1)) >> 1;
        const int* r0 = sidx[rl];
        const int* r1 = sidx[rl + 1];
        float* op = g_g + ((n * DIM + oc) * H1 + p) * H1 + q0;
        for (int jj = 0; jj < 32; jj += 4) {
            int cl = jj >> 1;
            int k00 = r0[cl], k01 = r0[cl + 1], k02 = r0[cl + 2], k03 = r0[cl + 3];
            int k10 = r1[cl], k11 = r1[cl + 1], k12 = r1[cl + 2], k13 = r1[cl + 3];
            float4 v;
            v.x = __ldg(&Toc[(k00 * 16 + a4)     * 128]) + __ldg(&Toc[(k01 * 16 + a4 + 2)  * 128])
                + __ldg(&Toc[(k10 * 16 + a4 + 8) * 128]) + __ldg(&Toc[(k11 * 16 + a4 + 10) * 128]);
            v.y = __ldg(&Toc[(k01 * 16 + a4 + 1) * 128]) + __ldg(&Toc[(k02 * 16 + a4 + 3)  * 128])
                + __ldg(&Toc[(k11 * 16 + a4 + 9) * 128]) + __ldg(&Toc[(k12 * 16 + a4 + 11) * 128]);
            v.z = __ldg(&Toc[(k01 * 16 + a4)     * 128]) + __ldg(&Toc[(k02 * 16 + a4 + 2)  * 128])
                + __ldg(&Toc[(k11 * 16 + a4 + 8) * 128]) + __ldg(&Toc[(k12 * 16 + a4 + 10) * 128]);
            v.w = __ldg(&Toc[(k02 * 16 + a4 + 1) * 128]) + __ldg(&Toc[(k03 * 16 + a4 + 3)  * 128])
                + __ldg(&Toc[(k12 * 16 + a4 + 9) * 128]) + __ldg(&Toc[(k13 * 16 + a4 + 11) * 128]);
            v.x = fmaxf(v.x, 0.f); v.y = fmaxf(v.y, 0.f);
            v.z = fmaxf(v.z, 0.f); v.w = fmaxf(v.w, 0.f);
            *(float4*)(op + jj) = v;
        }
    }
}

// deconv2 (R16 version)
__global__ __launch_bounds__(256) void deconv2_kernel(
    const float* __restrict__ w, float* __restrict__ recon) {
    __shared__ float wsp[CIN * DIM * 16];
    __shared__ float insb[2][2880];
    int n = blockIdx.z;
    int p0 = blockIdx.y * 32, q0 = blockIdx.x * 32;
    int tid = threadIdx.x, pl = tid >> 4, qi = tid & 15;
    int qp = qi & 1, jj = qi >> 1, a = pl & 1;
    int r0l = (pl + a) >> 1, c0l = qp + 2 * jj;
    int rb = p0 / 2 - 1, cb = q0 / 2 - 1;
    for (int i = tid; i < CIN * DIM * 16; i += 256) {
        int oc = i >> 11, rem = i & 2047;
        int ic = rem >> 4, k = rem & 15, kh = k >> 2, kw = k & 3;
        int slot = ic * 16 + ((kh & 1) * 2 + (kw & 1)) * 4 + ((kh >> 1) << 1) + (kw >> 1);
        wsp[oc * 2048 + slot] = w[i];
    }
    for (int i = tid; i < 2592; i += 256) {
        int ic = i / 324, rem = i - ic * 324, r = rem / 18, c = rem - r * 18;
        int rr = rb + r, cc = cb + c;
        bool ok = ((unsigned)rr < H1) && ((unsigned)cc < H1);
        const float* src = ok ? &g_g[((n * DIM + ic) * H1 + rr) * H1 + cc] : g_g;
        cp4z(cvta_s(&insb[0][ic * 360 + r * 20 + c]), src, ok ? 4 : 0);
    }
    CP_COMMIT();

    u64 acc[2][3] = {{0, 0, 0}, {0, 0, 0}};
    for (int s = 0; s < 16; s++) {
        CP_WAIT0();
        __syncthreads();
        if (s < 15) {
            int ic0 = (s + 1) * 8;
            float* nb = insb[(s + 1) & 1];
            for (int i = tid; i < 2592; i += 256) {
                int ic = i / 324, rem = i - ic * 324, r = rem / 18, c = rem - r * 18;
                int rr = rb + r, cc = cb + c;
                bool ok = ((unsigned)rr < H1) && ((unsigned)cc < H1);
                const float* src = ok ? &g_g[((n * DIM + ic0 + ic) * H1 + rr) * H1 + cc] : g_g;
                cp4z(cvta_s(nb + ic * 360 + r * 20 + c), src, ok ? 4 : 0);
            }
            CP_COMMIT();
        }
        const float* buf = insb[s & 1];
        int ic0 = s * 8;
#pragma unroll
        for (int icl = 0; icl < 8; icl++) {
            const float* rpa = buf + icl * 360 + r0l * 20;
            const float* rpb = rpa + 160;
            float t00 = rpa[c0l], t01 = rpa[c0l + 1], t02 = rpa[c0l + 2];
            float t10 = rpa[20 + c0l], t11 = rpa[20 + c0l + 1], t12 = rpa[20 + c0l + 2];
            float u00 = rpb[c0l], u01 = rpb[c0l + 1], u02 = rpb[c0l + 2];
            float u10 = rpb[20 + c0l], u11 = rpb[20 + c0l + 1], u12 = rpb[20 + c0l + 2];
            u64 i0a = pack2(t00, t01), i0b = pack2(t01, t02);
            u64 i1a = pack2(t10, t11), i1b = pack2(t11, t12);
            u64 j0a = pack2(u00, u01), j0b = pack2(u01, u02);
            u64 j1a = pack2(u10, u11), j1b = pack2(u11, u12);
            int kb = (ic0 + icl) * 16 + (a * 2 + qp) * 4;
#pragma unroll
            for (int o = 0; o < 3; o++) {
                float4 wg = *(const float4*)&wsp[o * 2048 + kb];
                u64 wx = pack2(wg.x, wg.x), wy = pack2(wg.y, wg.y);
                u64 wz = pack2(wg.z, wg.z), ww = pack2(wg.w, wg.w);
                fma2(acc[0][o], i0a, wx); fma2(acc[0][o], i0b, wy);
                fma2(acc[0][o], i1a, wz); fma2(acc[0][o], i1b, ww);
                fma2(acc[1][o], j0a, wx); fma2(acc[1][o], j0b, wy);
                fma2(acc[1][o], j1a, wz); fma2(acc[1][o], j1b, ww);
            }
        }
    }
    int q = q0 + qp + 4 * jj;
#pragma unroll
    for (int h = 0; h < 2; h++) {
        int p = p0 + pl + h * 16;
#pragma unroll
        for (int o = 0; o < 3; o++) {
            float2 v = unpack2(acc[h][o]);
            float* op = recon + ((n * CIN + o) * H0 + p) * H0;
            op[q] = tanhf(v.x);
            op[q + 2] = tanhf(v.y);
        }
    }
}

#define VQ_SMEM ((128 * 68 + 128 * 132) * (int)sizeof(float))

extern "C" void kernel_launch(void* const* d_in, const int* in_sizes, int n_in,
                              void* d_out, int out_size) {
    const float* x    = (const float*)d_in[0];
    const float* w_e1 = (const float*)d_in[1];
    const float* w_e2 = (const float*)d_in[2];
    const float* emb  = (const float*)d_in[3];
    const float* w_d1 = (const float*)d_in[4];
    const float* w_d2 = (const float*)d_in[5];
    float* out = (float*)d_out;
    float* recon = out;
    float* ze = out + OFF_ZE;
    float* zq = out + OFF_ZQ;

    cudaFuncSetAttribute(vq_kernel, cudaFuncAttributeMaxDynamicSharedMemorySize, VQ_SMEM);
    cudaFuncSetAttribute(conv2_kernel, cudaFuncAttributeMaxDynamicSharedMemorySize, C2_SMEM);

    knorm_kernel<<<2, 256>>>(emb);
    tmat_kernel<<<128, 256>>>(emb, w_d1);
    conv1_kernel<<<dim3(64, B), 256>>>(x, w_e1);
    conv2_kernel<<<dim3(8, 8, B), 256, C2_SMEM>>>(w_e2, ze);
    vq_kernel<<<1024, 256, VQ_SMEM>>>(ze, emb, zq);
    deconv1_gather_kernel<<<dim3(4, 16, B), 256>>>();
    deconv2_kernel<<<dim3(8, 8, B), 256>>>(w_d2, recon);
}